// round 16
// baseline (speedup 1.0000x reference)
#include <cuda_runtime.h>
#include <cuda_fp16.h>
#include <cstdint>

// ----------------------------------------------------------------------------
// Problem constants
// ----------------------------------------------------------------------------
#define DIM 128
#define BATCH 4096
#define HID 512
#define OUTD 256
#define KTOT (DIM * DIM)   // 16384
#define G1_ITERS 32        // 32 stages x 4 i-blocks

// GEMM1: 1024 CTAs of M64 x N32; 8 warps = 4 k-groups x 2 warps(32M x 32N each)
#define XS_STRIDE 136                       // halfs
#define XS_BYTES (64 * XS_STRIDE * 2)       // 17408
#define BROW_BYTES 80                       // 32 n-halfs (64B) + 16B pad
#define BBLK_BYTES (128 * BROW_BYTES)       // 10240 per i-block
#define BSTAGE_BYTES (4 * BBLK_BYTES)       // 40960 per stage (4 i-blocks)
#define G1_SMEM_BYTES (XS_BYTES + 2 * BSTAGE_BYTES)   // 99328
#define PS_STRIDE 36                        // psum floats per row (pad)
#define PS_BYTES (64 * PS_STRIDE * 4)       // 9216 per group

// Layer2: K=512 staged (A in 2 pipelined k-chunks); B k-major
#define L2_STRIDE 520
#define L2_A_BYTES (128 * L2_STRIDE * 2)    // 133120
#define L2B_ROW 144
#define L2_B_BYTES (512 * L2B_ROW)          // 73728
#define L2_SMEM_BYTES (L2_A_BYTES + L2_B_BYTES)   // 206848

// ----------------------------------------------------------------------------
// Device scratch
// ----------------------------------------------------------------------------
__device__ __half g_w1k[KTOT * HID];     // W1sym fp16, k-major [k][n] (16.8MB)
__device__ __half g_h[BATCH * HID];      // hidden activations fp16 (4MB)
__device__ __half g_w2k[HID * OUTD];     // W2 fp16, k-major (256KB)

// ----------------------------------------------------------------------------
// Helpers
// ----------------------------------------------------------------------------
__device__ __forceinline__ uint32_t smem_u32(const void* p) {
    uint32_t a;
    asm("{ .reg .u64 t; cvta.to.shared.u64 t, %1; cvt.u32.u64 %0, t; }" : "=r"(a) : "l"(p));
    return a;
}
__device__ __forceinline__ void cp_async16(uint32_t smem_addr, const void* gptr) {
    asm volatile("cp.async.cg.shared.global [%0], [%1], 16;" :: "r"(smem_addr), "l"(gptr) : "memory");
}
#define CP_COMMIT() asm volatile("cp.async.commit_group;" ::: "memory")
#define CP_WAIT(n)  asm volatile("cp.async.wait_group %0;" :: "n"(n) : "memory")

#define LDSM4(r, addr) \
    asm volatile("ldmatrix.sync.aligned.m8n8.x4.shared.b16 {%0,%1,%2,%3}, [%4];" \
        : "=r"((r)[0]), "=r"((r)[1]), "=r"((r)[2]), "=r"((r)[3]) : "r"(addr))
#define LDSM4T(r, addr) \
    asm volatile("ldmatrix.sync.aligned.m8n8.x4.trans.shared.b16 {%0,%1,%2,%3}, [%4];" \
        : "=r"((r)[0]), "=r"((r)[1]), "=r"((r)[2]), "=r"((r)[3]) : "r"(addr))

#define MMA_F16(d, a, bb0, bb1) \
    asm volatile("mma.sync.aligned.m16n8k16.row.col.f32.f16.f16.f32 " \
        "{%0,%1,%2,%3}, {%4,%5,%6,%7}, {%8,%9}, {%0,%1,%2,%3};" \
        : "+f"((d)[0]), "+f"((d)[1]), "+f"((d)[2]), "+f"((d)[3]) \
        : "r"((a)[0]), "r"((a)[1]), "r"((a)[2]), "r"((a)[3]), "r"(bb0), "r"(bb1))

// ----------------------------------------------------------------------------
// Kernel 1: prep — W1sym (k-major, elementwise) + W2 fp16 cvt.  float4 ILP.
//   blocks 0..8191: two W1sym k-rows each; blocks 8192..8319: W2 chunks.
// ----------------------------------------------------------------------------
__global__ __launch_bounds__(256) void k_prep(const float* __restrict__ W1,
                                              const float* __restrict__ W2) {
    const int b = blockIdx.x;
    const int t = threadIdx.x;
    if (b < KTOT / 2) {
        const int k = b * 2 + (t >> 7);
        const int i = k >> 7, j = k & 127;
        const int n = (t & 127) * 4;
        float4 v = make_float4(0.f, 0.f, 0.f, 0.f);
        if (j > i) {
            float4 a = *(const float4*)(W1 + (size_t)k * HID + n);
            float4 c = *(const float4*)(W1 + ((size_t)(j * DIM + i)) * HID + n);
            v.x = a.x + c.x; v.y = a.y + c.y; v.z = a.z + c.z; v.w = a.w + c.w;
        } else if (j == i) {
            v = *(const float4*)(W1 + (size_t)k * HID + n);
        }
        __half2 h0 = __floats2half2_rn(v.x, v.y);
        __half2 h1 = __floats2half2_rn(v.z, v.w);
        *(uint2*)(g_w1k + (size_t)k * HID + n) = make_uint2(*(uint32_t*)&h0, *(uint32_t*)&h1);
    } else {
        const int idx = ((b - KTOT / 2) * 256 + t) * 4;
        float4 v = *(const float4*)(W2 + idx);
        __half2 h0 = __floats2half2_rn(v.x, v.y);
        __half2 h1 = __floats2half2_rn(v.z, v.w);
        *(uint2*)(g_w2k + idx) = make_uint2(*(uint32_t*)&h0, *(uint32_t*)&h1);
    }
}

// ----------------------------------------------------------------------------
// Kernel 2: H = relu( (d * x (x) x) @ W1 + b1 ) — symmetric triangle.
//   1024 CTAs (M64 x N32), HW-balanced. 4-way warp-group k-split:
//   group wg handles i-blocks c = 4*it + wg; smem reduction at end.
// ----------------------------------------------------------------------------
#define G1_PREFETCH(it_) do {                                                      \
    const int c0__ = 4 * (it_);                                                    \
    const uint32_t sbuf__ = bs_b + (uint32_t)((it_) & 1) * BSTAGE_BYTES;           \
    _Pragma("unroll")                                                              \
    for (int r__ = 0; r__ < 8; r__++) {                                            \
        int id__ = tid + r__ * 256;                                                \
        int blk__ = id__ >> 9;                                                     \
        int rem__ = id__ & 511;                                                    \
        int row__ = rem__ >> 2;                                                    \
        int seg__ = rem__ & 3;                                                     \
        int c__ = c0__ + blk__;                                                    \
        if (row__ >= ((c__ >> 4) << 4))                                            \
            cp_async16(sbuf__ + (uint32_t)(blk__ * BBLK_BYTES + row__ * BROW_BYTES + seg__ * 16), \
                       w1k + ((size_t)(c__ * DIM + row__)) * HID + n0 + seg__ * 8); \
    }                                                                              \
} while (0)

__global__ __launch_bounds__(256, 2) void k_gemm1(const float* __restrict__ x,
                                                  const float* __restrict__ bias1) {
    extern __shared__ char smem_raw[];
    __half* xsh = (__half*)smem_raw;                 // [64][XS_STRIDE]
    const uint32_t xs_b = smem_u32(xsh);
    const uint32_t bs_b = xs_b + XS_BYTES;

    const int tid  = threadIdx.x;
    const int lane = tid & 31;
    const int wid  = tid >> 5;
    const int wg   = wid >> 1;           // k-group 0..3
    const int wm   = wid & 1;            // 32-row slab within M64
    const int gid  = lane >> 2;
    const int tg   = lane & 3;
    const int l7   = lane & 7;
    const int m0 = (blockIdx.x & 63) * 64;
    const int n0 = (blockIdx.x >> 6) * 32;

    const __half* w1k = g_w1k;

    // ---- prefetch stage 0 (overlaps x staging) ----
    G1_PREFETCH(0);
    CP_COMMIT();

    // ---- stage x tile (64 rows) as fp16 ----
    #pragma unroll
    for (int r = 0; r < 8; r++) {
        int id = tid + r * 256;          // 0..2047 float4s
        int m = id >> 5, c4 = id & 31;
        float4 v = *(const float4*)(x + (size_t)(m0 + m) * DIM + c4 * 4);
        __half2 h0 = __floats2half2_rn(v.x, v.y);
        __half2 h1 = __floats2half2_rn(v.z, v.w);
        *(uint2*)(xsh + m * XS_STRIDE + c4 * 4) = make_uint2(*(uint32_t*)&h0, *(uint32_t*)&h1);
    }

    int rowt[4];
    rowt[0] = m0 + wm * 32 + gid;
    rowt[1] = rowt[0] + 8;
    rowt[2] = rowt[0] + 16;
    rowt[3] = rowt[0] + 24;

    const uint32_t aAddr = xs_b +
        (uint32_t)(((wm * 32 + l7 + ((lane >> 3) & 1) * 8) * XS_STRIDE + ((lane >> 4) & 1) * 8) * 2);
    const uint32_t bLane = (uint32_t)((lane & 15) * BROW_BYTES + ((lane >> 4) << 4));

    float acc[2][4][4];
    #pragma unroll
    for (int mt = 0; mt < 2; mt++)
        #pragma unroll
        for (int nt = 0; nt < 4; nt++)
            #pragma unroll
            for (int q = 0; q < 4; q++) acc[mt][nt][q] = 0.0f;

    #pragma unroll 1
    for (int it = 0; it < G1_ITERS; it++) {
        CP_WAIT(0);
        __syncthreads();
        if (it + 1 < G1_ITERS) G1_PREFETCH(it + 1);
        CP_COMMIT();

        const int c = 4 * it + wg;       // this group's i-block
        float xi[4];
        #pragma unroll
        for (int t = 0; t < 4; t++)
            xi[t] = 128.0f * __ldg(x + (size_t)rowt[t] * DIM + c);

        float p[2][4][4];
        #pragma unroll
        for (int mt = 0; mt < 2; mt++)
            #pragma unroll
            for (int nt = 0; nt < 4; nt++)
                #pragma unroll
                for (int q = 0; q < 4; q++) p[mt][nt][q] = 0.0f;

        const uint32_t bBlk = bs_b + (uint32_t)(it & 1) * BSTAGE_BYTES
                              + (uint32_t)(wg * BBLK_BYTES) + bLane;
        const int s0 = c >> 4;
        for (int s = s0; s < 8; s++) {
            uint32_t a0[4], a1[4], bA[4], bB[4];
            LDSM4(a0, aAddr + (uint32_t)(s * 32));
            LDSM4(a1, aAddr + (uint32_t)(16 * XS_STRIDE * 2 + s * 32));
            const uint32_t bs0 = bBlk + (uint32_t)(s * 16 * BROW_BYTES);
            LDSM4T(bA, bs0);             // n 0..15
            LDSM4T(bB, bs0 + 32);        // n 16..31
            MMA_F16(p[0][0], a0, bA[0], bA[1]);
            MMA_F16(p[1][0], a1, bA[0], bA[1]);
            MMA_F16(p[0][1], a0, bA[2], bA[3]);
            MMA_F16(p[1][1], a1, bA[2], bA[3]);
            MMA_F16(p[0][2], a0, bB[0], bB[1]);
            MMA_F16(p[1][2], a1, bB[0], bB[1]);
            MMA_F16(p[0][3], a0, bB[2], bB[3]);
            MMA_F16(p[1][3], a1, bB[2], bB[3]);
        }
        #pragma unroll
        for (int mt = 0; mt < 2; mt++)
            #pragma unroll
            for (int nt = 0; nt < 4; nt++) {
                acc[mt][nt][0] = fmaf(xi[mt * 2],     p[mt][nt][0], acc[mt][nt][0]);
                acc[mt][nt][1] = fmaf(xi[mt * 2],     p[mt][nt][1], acc[mt][nt][1]);
                acc[mt][nt][2] = fmaf(xi[mt * 2 + 1], p[mt][nt][2], acc[mt][nt][2]);
                acc[mt][nt][3] = fmaf(xi[mt * 2 + 1], p[mt][nt][3], acc[mt][nt][3]);
            }
    }

    // ---- cross-group reduction (groups 1..3 -> smem; group 0 adds) ----
    __syncthreads();
    float* psum = (float*)(smem_raw + XS_BYTES);     // reuse B buffers
    if (wg > 0) {
        float* ps = psum + (wg - 1) * (64 * PS_STRIDE);
        #pragma unroll
        for (int mt = 0; mt < 2; mt++)
            #pragma unroll
            for (int nt = 0; nt < 4; nt++) {
                int row = wm * 32 + mt * 16 + gid;
                int col = nt * 8 + tg * 2;
                *(float2*)(ps + row * PS_STRIDE + col) =
                    make_float2(acc[mt][nt][0], acc[mt][nt][1]);
                *(float2*)(ps + (row + 8) * PS_STRIDE + col) =
                    make_float2(acc[mt][nt][2], acc[mt][nt][3]);
            }
    }
    __syncthreads();
    if (wg == 0) {
        #pragma unroll
        for (int mt = 0; mt < 2; mt++)
            #pragma unroll
            for (int nt = 0; nt < 4; nt++) {
                int row = wm * 32 + mt * 16 + gid;
                int col = nt * 8 + tg * 2;
                #pragma unroll
                for (int g = 0; g < 3; g++) {
                    float* ps = psum + g * (64 * PS_STRIDE);
                    float2 v0 = *(float2*)(ps + row * PS_STRIDE + col);
                    float2 v1 = *(float2*)(ps + (row + 8) * PS_STRIDE + col);
                    acc[mt][nt][0] += v0.x; acc[mt][nt][1] += v0.y;
                    acc[mt][nt][2] += v1.x; acc[mt][nt][3] += v1.y;
                }
                int gcol = n0 + col;
                float bb0 = bias1[gcol], bb1 = bias1[gcol + 1];
                int rowA = m0 + row;
                *(__half2*)(g_h + (size_t)rowA * HID + gcol) =
                    __floats2half2_rn(fmaxf(acc[mt][nt][0] + bb0, 0.0f),
                                      fmaxf(acc[mt][nt][1] + bb1, 0.0f));
                *(__half2*)(g_h + (size_t)(rowA + 8) * HID + gcol) =
                    __floats2half2_rn(fmaxf(acc[mt][nt][2] + bb0, 0.0f),
                                      fmaxf(acc[mt][nt][3] + bb1, 0.0f));
            }
    }
}

// ----------------------------------------------------------------------------
// Kernel 3: out = h @ W2 + b2  (fp16 mma; A loaded in 2 pipelined k-chunks)
// ----------------------------------------------------------------------------
__global__ __launch_bounds__(256, 1) void k_layer2(const float* __restrict__ b2,
                                                   float* __restrict__ out) {
    extern __shared__ char smem_raw[];
    __half* ash = (__half*)smem_raw;                 // [128][L2_STRIDE]
    const uint32_t as_b = smem_u32(ash);
    const uint32_t bs_b = as_b + L2_A_BYTES;         // [512 k][64 n + pad]

    const int tid  = threadIdx.x;
    const int lane = tid & 31;
    const int wid  = tid >> 5;
    const int wm   = wid & 3, wn = wid >> 2;
    const int gid  = lane >> 2, tg = lane & 3, l7 = lane & 7;
    const int m0 = (blockIdx.x & 31) * 128;
    const int n0 = (blockIdx.x >> 5) * 64;

    const __half* hg = g_h;
    const __half* w2k = g_w2k;

    // A chunk 0 (k 0..255)
    #pragma unroll
    for (int r = 0; r < 16; r++) {
        int id = tid + r * 256;
        int row = id >> 5, seg = id & 31;
        cp_async16(as_b + (uint32_t)(row * (L2_STRIDE * 2) + seg * 16),
                   hg + (size_t)(m0 + row) * HID + seg * 8);
    }
    CP_COMMIT();
    // B (all K)
    #pragma unroll
    for (int r = 0; r < 16; r++) {
        int id = tid + r * 256;
        int row = id >> 3, seg = id & 7;
        cp_async16(bs_b + (uint32_t)(row * L2B_ROW + seg * 16),
                   w2k + (size_t)row * OUTD + n0 + seg * 8);
    }
    CP_COMMIT();
    // A chunk 1 (k 256..511)
    #pragma unroll
    for (int r = 0; r < 16; r++) {
        int id = tid + r * 256;
        int row = id >> 5, seg = (id & 31) + 32;
        cp_async16(as_b + (uint32_t)(row * (L2_STRIDE * 2) + seg * 16),
                   hg + (size_t)(m0 + row) * HID + seg * 8);
    }
    CP_COMMIT();

    const uint32_t aAddr = as_b +
        (uint32_t)(((wm * 32 + l7 + ((lane >> 3) & 1) * 8) * L2_STRIDE + ((lane >> 4) & 1) * 8) * 2);
    const uint32_t bLane = bs_b +
        (uint32_t)((lane & 15) * L2B_ROW + ((wn * 32 + ((lane >> 4) << 3)) * 2));

    float acc[2][4][4];
    #pragma unroll
    for (int mt = 0; mt < 2; mt++)
        #pragma unroll
        for (int nt = 0; nt < 4; nt++)
            #pragma unroll
            for (int q = 0; q < 4; q++) acc[mt][nt][q] = 0.0f;

    CP_WAIT(1);                // A0 + B landed
    __syncthreads();

    #pragma unroll 4
    for (int s = 0; s < 16; s++) {
        uint32_t a0[4], a1[4], bA[4], bB[4];
        LDSM4(a0, aAddr + (uint32_t)(s * 32));
        LDSM4(a1, aAddr + (uint32_t)(16 * L2_STRIDE * 2 + s * 32));
        const uint32_t bs0 = bLane + (uint32_t)(s * 16 * L2B_ROW);
        LDSM4T(bA, bs0);
        LDSM4T(bB, bs0 + 32);
        MMA_F16(acc[0][0], a0, bA[0], bA[1]);
        MMA_F16(acc[1][0], a1, bA[0], bA[1]);
        MMA_F16(acc[0][1], a0, bA[2], bA[3]);
        MMA_F16(acc[1][1], a1, bA[2], bA[3]);
        MMA_F16(acc[0][2], a0, bB[0], bB[1]);
        MMA_F16(acc[1][2], a1, bB[0], bB[1]);
        MMA_F16(acc[0][3], a0, bB[2], bB[3]);
        MMA_F16(acc[1][3], a1, bB[2], bB[3]);
    }

    CP_WAIT(0);                // A1 landed
    __syncthreads();

    #pragma unroll 4
    for (int s = 16; s < 32; s++) {
        uint32_t a0[4], a1[4], bA[4], bB[4];
        LDSM4(a0, aAddr + (uint32_t)(s * 32));
        LDSM4(a1, aAddr + (uint32_t)(16 * L2_STRIDE * 2 + s * 32));
        const uint32_t bs0 = bLane + (uint32_t)(s * 16 * L2B_ROW);
        LDSM4T(bA, bs0);
        LDSM4T(bB, bs0 + 32);
        MMA_F16(acc[0][0], a0, bA[0], bA[1]);
        MMA_F16(acc[1][0], a1, bA[0], bA[1]);
        MMA_F16(acc[0][1], a0, bA[2], bA[3]);
        MMA_F16(acc[1][1], a1, bA[2], bA[3]);
        MMA_F16(acc[0][2], a0, bB[0], bB[1]);
        MMA_F16(acc[1][2], a1, bB[0], bB[1]);
        MMA_F16(acc[0][3], a0, bB[2], bB[3]);
        MMA_F16(acc[1][3], a1, bB[2], bB[3]);
    }

    #pragma unroll
    for (int mt = 0; mt < 2; mt++) {
        #pragma unroll
        for (int nt = 0; nt < 4; nt++) {
            int col = n0 + wn * 32 + nt * 8 + tg * 2;
            float bb0 = b2[col], bb1 = b2[col + 1];
            int rowA = m0 + wm * 32 + mt * 16 + gid;
            *(float2*)(out + (size_t)rowA * OUTD + col) =
                make_float2(acc[mt][nt][0] + bb0, acc[mt][nt][1] + bb1);
            *(float2*)(out + (size_t)(rowA + 8) * OUTD + col) =
                make_float2(acc[mt][nt][2] + bb0, acc[mt][nt][3] + bb1);
        }
    }
}

// ----------------------------------------------------------------------------
// Launch
// ----------------------------------------------------------------------------
extern "C" void kernel_launch(void* const* d_in, const int* in_sizes, int n_in,
                              void* d_out, int out_size) {
    const float *x = nullptr, *W1 = nullptr, *b1 = nullptr, *W2 = nullptr, *b2 = nullptr;
    for (int i = 0; i < n_in; i++) {
        switch (in_sizes[i]) {
            case BATCH * DIM:  x  = (const float*)d_in[i]; break;
            case KTOT * HID:   W1 = (const float*)d_in[i]; break;
            case HID:          b1 = (const float*)d_in[i]; break;
            case HID * OUTD:   W2 = (const float*)d_in[i]; break;
            case OUTD:         b2 = (const float*)d_in[i]; break;
            default: break;
        }
    }

    cudaFuncSetAttribute(k_gemm1,  cudaFuncAttributeMaxDynamicSharedMemorySize, G1_SMEM_BYTES);
    cudaFuncSetAttribute(k_layer2, cudaFuncAttributeMaxDynamicSharedMemorySize, L2_SMEM_BYTES);

    k_prep<<<KTOT / 2 + (HID * OUTD) / 1024, 256>>>(W1, W2);
    k_gemm1<<<1024, 256, G1_SMEM_BYTES>>>(x, b1);
    k_layer2<<<128, 256, L2_SMEM_BYTES>>>(b2, (float*)d_out);
}

// round 17
// speedup vs baseline: 1.0832x; 1.0832x over previous
#include <cuda_runtime.h>
#include <cuda_fp16.h>
#include <cstdint>

// ----------------------------------------------------------------------------
// Problem constants
// ----------------------------------------------------------------------------
#define DIM 128
#define BATCH 4096
#define HID 512
#define OUTD 256
#define KTOT (DIM * DIM)   // 16384
#define NITER 64           // 64 double-chunks (2 i-blocks each)

// GEMM1 tiling: CTA 128(M) x 64(N), 8 warps (32x32), 256 CTAs, occ 2
#define XS_STRIDE 136                       // halfs, conflict-free ldmatrix
#define XS_BYTES (128 * XS_STRIDE * 2)      // 34816
#define BROW_BYTES 144                      // 64 n-halfs + 8 pad (bank residue 4)
#define BBLK_BYTES (128 * BROW_BYTES)       // 18432 per i-block
#define BSTAGE_BYTES (2 * BBLK_BYTES)       // 36864 per stage (2 i-blocks)
#define G1_SMEM_BYTES (XS_BYTES + 2 * BSTAGE_BYTES)   // 108544

// Layer2: K=512 staged (A in 2 pipelined k-chunks); B k-major
#define L2_STRIDE 520
#define L2_A_BYTES (128 * L2_STRIDE * 2)    // 133120
#define L2B_ROW 144
#define L2_B_BYTES (512 * L2B_ROW)          // 73728
#define L2_SMEM_BYTES (L2_A_BYTES + L2_B_BYTES)   // 206848

// ----------------------------------------------------------------------------
// Device scratch
// ----------------------------------------------------------------------------
__device__ __half g_w1k[KTOT * HID];     // W1sym fp16, k-major [k][n] (16.8MB)
__device__ __half g_h[BATCH * HID];      // hidden activations fp16 (4MB)
__device__ __half g_w2k[HID * OUTD];     // W2 fp16, k-major (256KB)

// ----------------------------------------------------------------------------
// Helpers
// ----------------------------------------------------------------------------
__device__ __forceinline__ uint32_t smem_u32(const void* p) {
    uint32_t a;
    asm("{ .reg .u64 t; cvta.to.shared.u64 t, %1; cvt.u32.u64 %0, t; }" : "=r"(a) : "l"(p));
    return a;
}
__device__ __forceinline__ void cp_async16(uint32_t smem_addr, const void* gptr) {
    asm volatile("cp.async.cg.shared.global [%0], [%1], 16;" :: "r"(smem_addr), "l"(gptr) : "memory");
}
#define CP_COMMIT() asm volatile("cp.async.commit_group;" ::: "memory")
#define CP_WAIT(n)  asm volatile("cp.async.wait_group %0;" :: "n"(n) : "memory")

#define LDSM4(r, addr) \
    asm volatile("ldmatrix.sync.aligned.m8n8.x4.shared.b16 {%0,%1,%2,%3}, [%4];" \
        : "=r"((r)[0]), "=r"((r)[1]), "=r"((r)[2]), "=r"((r)[3]) : "r"(addr))
#define LDSM4T(r, addr) \
    asm volatile("ldmatrix.sync.aligned.m8n8.x4.trans.shared.b16 {%0,%1,%2,%3}, [%4];" \
        : "=r"((r)[0]), "=r"((r)[1]), "=r"((r)[2]), "=r"((r)[3]) : "r"(addr))

#define MMA_F16(d, a, bb0, bb1) \
    asm volatile("mma.sync.aligned.m16n8k16.row.col.f32.f16.f16.f32 " \
        "{%0,%1,%2,%3}, {%4,%5,%6,%7}, {%8,%9}, {%0,%1,%2,%3};" \
        : "+f"((d)[0]), "+f"((d)[1]), "+f"((d)[2]), "+f"((d)[3]) \
        : "r"((a)[0]), "r"((a)[1]), "r"((a)[2]), "r"((a)[3]), "r"(bb0), "r"(bb1))

// ----------------------------------------------------------------------------
// Kernel 1: prep — W1sym (k-major, elementwise) + W2 fp16 cvt.  float4 ILP.
// ----------------------------------------------------------------------------
__global__ __launch_bounds__(256) void k_prep(const float* __restrict__ W1,
                                              const float* __restrict__ W2) {
    const int b = blockIdx.x;
    const int t = threadIdx.x;
    if (b < KTOT / 2) {
        const int k = b * 2 + (t >> 7);
        const int i = k >> 7, j = k & 127;
        const int n = (t & 127) * 4;
        float4 v = make_float4(0.f, 0.f, 0.f, 0.f);
        if (j > i) {
            float4 a = *(const float4*)(W1 + (size_t)k * HID + n);
            float4 c = *(const float4*)(W1 + ((size_t)(j * DIM + i)) * HID + n);
            v.x = a.x + c.x; v.y = a.y + c.y; v.z = a.z + c.z; v.w = a.w + c.w;
        } else if (j == i) {
            v = *(const float4*)(W1 + (size_t)k * HID + n);
        }
        __half2 h0 = __floats2half2_rn(v.x, v.y);
        __half2 h1 = __floats2half2_rn(v.z, v.w);
        *(uint2*)(g_w1k + (size_t)k * HID + n) = make_uint2(*(uint32_t*)&h0, *(uint32_t*)&h1);
    } else {
        const int idx = ((b - KTOT / 2) * 256 + t) * 4;
        float4 v = *(const float4*)(W2 + idx);
        __half2 h0 = __floats2half2_rn(v.x, v.y);
        __half2 h1 = __floats2half2_rn(v.z, v.w);
        *(uint2*)(g_w2k + idx) = make_uint2(*(uint32_t*)&h0, *(uint32_t*)&h1);
    }
}

// ----------------------------------------------------------------------------
// Kernel 2: H = relu( (d * x (x) x) @ W1 + b1 ) — symmetric triangle,
//   B k-major via trans ldmatrix, 2 i-blocks/stage, double buffer.
//   (R15-proven mainloop, reverted from the R16 k-split experiment.)
// ----------------------------------------------------------------------------
#define G1_PREFETCH2(it_) do {                                                     \
    const int c0__ = 2 * (it_);                                                    \
    const uint32_t sbuf__ = bs_b + (uint32_t)((it_) & 1) * BSTAGE_BYTES;           \
    _Pragma("unroll")                                                              \
    for (int r__ = 0; r__ < 8; r__++) {                                            \
        int id__ = tid + r__ * 256;                                                \
        int blk__ = id__ >> 10;                                                    \
        int rem__ = id__ & 1023;                                                   \
        int row__ = rem__ >> 3;                                                    \
        int seg__ = rem__ & 7;                                                     \
        int c__ = c0__ + blk__;                                                    \
        if (row__ >= ((c__ >> 4) << 4))                                            \
            cp_async16(sbuf__ + (uint32_t)(blk__ * BBLK_BYTES + row__ * BROW_BYTES + seg__ * 16), \
                       w1k + ((size_t)(c__ * DIM + row__)) * HID + n0 + seg__ * 8); \
    }                                                                              \
} while (0)

__global__ __launch_bounds__(256, 2) void k_gemm1(const float* __restrict__ x,
                                                  const float* __restrict__ bias1) {
    extern __shared__ char smem_raw[];
    __half* xsh = (__half*)smem_raw;
    const uint32_t xs_b = smem_u32(xsh);
    const uint32_t bs_b = xs_b + XS_BYTES;

    const int tid  = threadIdx.x;
    const int lane = tid & 31;
    const int wid  = tid >> 5;
    const int wm   = wid & 3, wn = wid >> 2;
    const int gid  = lane >> 2;
    const int tg   = lane & 3;
    const int l7   = lane & 7;
    const int m0 = (blockIdx.x & 31) * 128;
    const int n0 = (blockIdx.x >> 5) * 64;

    const __half* w1k = g_w1k;

    // ---- prefetch stage 0 (overlaps x staging) ----
    G1_PREFETCH2(0);
    CP_COMMIT();

    // ---- stage x tile as fp16 [m][j] ----
    #pragma unroll
    for (int r = 0; r < 16; r++) {
        int id = tid + r * 256;
        int m = id >> 5, c4 = id & 31;
        float4 v = *(const float4*)(x + (size_t)(m0 + m) * DIM + c4 * 4);
        __half2 h0 = __floats2half2_rn(v.x, v.y);
        __half2 h1 = __floats2half2_rn(v.z, v.w);
        uint2 pk = make_uint2(*(uint32_t*)&h0, *(uint32_t*)&h1);
        *(uint2*)(xsh + m * XS_STRIDE + c4 * 4) = pk;
    }

    int rowt[4];
    rowt[0] = m0 + wm * 32 + gid;
    rowt[1] = rowt[0] + 8;
    rowt[2] = rowt[0] + 16;
    rowt[3] = rowt[0] + 24;

    const uint32_t aAddr = xs_b +
        (uint32_t)(((wm * 32 + l7 + ((lane >> 3) & 1) * 8) * XS_STRIDE + ((lane >> 4) & 1) * 8) * 2);
    const uint32_t bLane = (uint32_t)((lane & 15) * BROW_BYTES + ((wn * 32 + ((lane >> 4) << 3)) * 2));

    float acc[2][4][4];
    #pragma unroll
    for (int mt = 0; mt < 2; mt++)
        #pragma unroll
        for (int nt = 0; nt < 4; nt++)
            #pragma unroll
            for (int q = 0; q < 4; q++) acc[mt][nt][q] = 0.0f;

    #pragma unroll 1
    for (int it = 0; it < NITER; it++) {
        CP_WAIT(0);
        __syncthreads();

        if (it + 1 < NITER) G1_PREFETCH2(it + 1);
        CP_COMMIT();

        const uint32_t bStage = bs_b + (uint32_t)(it & 1) * BSTAGE_BYTES;

        #pragma unroll
        for (int blk = 0; blk < 2; blk++) {
            const int c = 2 * it + blk;
            float xi[4];
            #pragma unroll
            for (int t = 0; t < 4; t++)
                xi[t] = 128.0f * __ldg(x + (size_t)rowt[t] * DIM + c);

            float p[2][4][4];
            #pragma unroll
            for (int mt = 0; mt < 2; mt++)
                #pragma unroll
                for (int nt = 0; nt < 4; nt++)
                    #pragma unroll
                    for (int q = 0; q < 4; q++) p[mt][nt][q] = 0.0f;

            const uint32_t bBlk = bStage + (uint32_t)(blk * BBLK_BYTES) + bLane;
            const int s0 = c >> 4;
            for (int s = s0; s < 8; s++) {
                uint32_t a0[4], a1[4], bA[4], bB[4];
                LDSM4(a0, aAddr + (uint32_t)(s * 32));
                LDSM4(a1, aAddr + (uint32_t)(16 * XS_STRIDE * 2 + s * 32));
                const uint32_t bs0 = bBlk + (uint32_t)(s * 16 * BROW_BYTES);
                LDSM4T(bA, bs0);           // n-tiles 0,1 of warp slab
                LDSM4T(bB, bs0 + 32);      // n-tiles 2,3 (+16 halfs)
                MMA_F16(p[0][0], a0, bA[0], bA[1]);
                MMA_F16(p[1][0], a1, bA[0], bA[1]);
                MMA_F16(p[0][1], a0, bA[2], bA[3]);
                MMA_F16(p[1][1], a1, bA[2], bA[3]);
                MMA_F16(p[0][2], a0, bB[0], bB[1]);
                MMA_F16(p[1][2], a1, bB[0], bB[1]);
                MMA_F16(p[0][3], a0, bB[2], bB[3]);
                MMA_F16(p[1][3], a1, bB[2], bB[3]);
            }
            #pragma unroll
            for (int mt = 0; mt < 2; mt++)
                #pragma unroll
                for (int nt = 0; nt < 4; nt++) {
                    acc[mt][nt][0] = fmaf(xi[mt * 2],     p[mt][nt][0], acc[mt][nt][0]);
                    acc[mt][nt][1] = fmaf(xi[mt * 2],     p[mt][nt][1], acc[mt][nt][1]);
                    acc[mt][nt][2] = fmaf(xi[mt * 2 + 1], p[mt][nt][2], acc[mt][nt][2]);
                    acc[mt][nt][3] = fmaf(xi[mt * 2 + 1], p[mt][nt][3], acc[mt][nt][3]);
                }
        }
    }

    // ---- Epilogue: +b1, relu, fp16 store ----
    #pragma unroll
    for (int mt = 0; mt < 2; mt++) {
        #pragma unroll
        for (int nt = 0; nt < 4; nt++) {
            int col = n0 + wn * 32 + nt * 8 + tg * 2;
            float bb0 = bias1[col], bb1 = bias1[col + 1];
            int rowA = m0 + wm * 32 + mt * 16 + gid;
            *(__half2*)(g_h + (size_t)rowA * HID + col) =
                __floats2half2_rn(fmaxf(acc[mt][nt][0] + bb0, 0.0f),
                                  fmaxf(acc[mt][nt][1] + bb1, 0.0f));
            *(__half2*)(g_h + (size_t)(rowA + 8) * HID + col) =
                __floats2half2_rn(fmaxf(acc[mt][nt][2] + bb0, 0.0f),
                                  fmaxf(acc[mt][nt][3] + bb1, 0.0f));
        }
    }
}

// ----------------------------------------------------------------------------
// Kernel 3: out = h @ W2 + b2  (fp16 mma; A loaded in 2 pipelined k-chunks)
// ----------------------------------------------------------------------------
__global__ __launch_bounds__(256, 1) void k_layer2(const float* __restrict__ b2,
                                                   float* __restrict__ out) {
    extern __shared__ char smem_raw[];
    __half* ash = (__half*)smem_raw;                 // [128][L2_STRIDE]
    const uint32_t as_b = smem_u32(ash);
    const uint32_t bs_b = as_b + L2_A_BYTES;         // [512 k][64 n + pad]

    const int tid  = threadIdx.x;
    const int lane = tid & 31;
    const int wid  = tid >> 5;
    const int wm   = wid & 3, wn = wid >> 2;
    const int gid  = lane >> 2, tg = lane & 3, l7 = lane & 7;
    const int m0 = (blockIdx.x & 31) * 128;
    const int n0 = (blockIdx.x >> 5) * 64;

    const __half* hg = g_h;
    const __half* w2k = g_w2k;

    // A chunk 0 (k 0..255)
    #pragma unroll
    for (int r = 0; r < 16; r++) {
        int id = tid + r * 256;
        int row = id >> 5, seg = id & 31;
        cp_async16(as_b + (uint32_t)(row * (L2_STRIDE * 2) + seg * 16),
                   hg + (size_t)(m0 + row) * HID + seg * 8);
    }
    CP_COMMIT();
    // B (all K)
    #pragma unroll
    for (int r = 0; r < 16; r++) {
        int id = tid + r * 256;
        int row = id >> 3, seg = id & 7;
        cp_async16(bs_b + (uint32_t)(row * L2B_ROW + seg * 16),
                   w2k + (size_t)row * OUTD + n0 + seg * 8);
    }
    CP_COMMIT();
    // A chunk 1 (k 256..511)
    #pragma unroll
    for (int r = 0; r < 16; r++) {
        int id = tid + r * 256;
        int row = id >> 5, seg = (id & 31) + 32;
        cp_async16(as_b + (uint32_t)(row * (L2_STRIDE * 2) + seg * 16),
                   hg + (size_t)(m0 + row) * HID + seg * 8);
    }
    CP_COMMIT();

    const uint32_t aAddr = as_b +
        (uint32_t)(((wm * 32 + l7 + ((lane >> 3) & 1) * 8) * L2_STRIDE + ((lane >> 4) & 1) * 8) * 2);
    const uint32_t bLane = bs_b +
        (uint32_t)((lane & 15) * L2B_ROW + ((wn * 32 + ((lane >> 4) << 3)) * 2));

    float acc[2][4][4];
    #pragma unroll
    for (int mt = 0; mt < 2; mt++)
        #pragma unroll
        for (int nt = 0; nt < 4; nt++)
            #pragma unroll
            for (int q = 0; q < 4; q++) acc[mt][nt][q] = 0.0f;

    CP_WAIT(1);                // A0 + B landed
    __syncthreads();

    #pragma unroll 4
    for (int s = 0; s < 16; s++) {
        uint32_t a0[4], a1[4], bA[4], bB[4];
        LDSM4(a0, aAddr + (uint32_t)(s * 32));
        LDSM4(a1, aAddr + (uint32_t)(16 * L2_STRIDE * 2 + s * 32));
        const uint32_t bs0 = bLane + (uint32_t)(s * 16 * L2B_ROW);
        LDSM4T(bA, bs0);
        LDSM4T(bB, bs0 + 32);
        MMA_F16(acc[0][0], a0, bA[0], bA[1]);
        MMA_F16(acc[1][0], a1, bA[0], bA[1]);
        MMA_F16(acc[0][1], a0, bA[2], bA[3]);
        MMA_F16(acc[1][1], a1, bA[2], bA[3]);
        MMA_F16(acc[0][2], a0, bB[0], bB[1]);
        MMA_F16(acc[1][2], a1, bB[0], bB[1]);
        MMA_F16(acc[0][3], a0, bB[2], bB[3]);
        MMA_F16(acc[1][3], a1, bB[2], bB[3]);
    }

    CP_WAIT(0);                // A1 landed
    __syncthreads();

    #pragma unroll 4
    for (int s = 16; s < 32; s++) {
        uint32_t a0[4], a1[4], bA[4], bB[4];
        LDSM4(a0, aAddr + (uint32_t)(s * 32));
        LDSM4(a1, aAddr + (uint32_t)(16 * L2_STRIDE * 2 + s * 32));
        const uint32_t bs0 = bLane + (uint32_t)(s * 16 * L2B_ROW);
        LDSM4T(bA, bs0);
        LDSM4T(bB, bs0 + 32);
        MMA_F16(acc[0][0], a0, bA[0], bA[1]);
        MMA_F16(acc[1][0], a1, bA[0], bA[1]);
        MMA_F16(acc[0][1], a0, bA[2], bA[3]);
        MMA_F16(acc[1][1], a1, bA[2], bA[3]);
        MMA_F16(acc[0][2], a0, bB[0], bB[1]);
        MMA_F16(acc[1][2], a1, bB[0], bB[1]);
        MMA_F16(acc[0][3], a0, bB[2], bB[3]);
        MMA_F16(acc[1][3], a1, bB[2], bB[3]);
    }

    #pragma unroll
    for (int mt = 0; mt < 2; mt++) {
        #pragma unroll
        for (int nt = 0; nt < 4; nt++) {
            int col = n0 + wn * 32 + nt * 8 + tg * 2;
            float bb0 = b2[col], bb1 = b2[col + 1];
            int rowA = m0 + wm * 32 + mt * 16 + gid;
            *(float2*)(out + (size_t)rowA * OUTD + col) =
                make_float2(acc[mt][nt][0] + bb0, acc[mt][nt][1] + bb1);
            *(float2*)(out + (size_t)(rowA + 8) * OUTD + col) =
                make_float2(acc[mt][nt][2] + bb0, acc[mt][nt][3] + bb1);
        }
    }
}

// ----------------------------------------------------------------------------
// Launch
// ----------------------------------------------------------------------------
extern "C" void kernel_launch(void* const* d_in, const int* in_sizes, int n_in,
                              void* d_out, int out_size) {
    const float *x = nullptr, *W1 = nullptr, *b1 = nullptr, *W2 = nullptr, *b2 = nullptr;
    for (int i = 0; i < n_in; i++) {
        switch (in_sizes[i]) {
            case BATCH * DIM:  x  = (const float*)d_in[i]; break;
            case KTOT * HID:   W1 = (const float*)d_in[i]; break;
            case HID:          b1 = (const float*)d_in[i]; break;
            case HID * OUTD:   W2 = (const float*)d_in[i]; break;
            case OUTD:         b2 = (const float*)d_in[i]; break;
            default: break;
        }
    }

    cudaFuncSetAttribute(k_gemm1,  cudaFuncAttributeMaxDynamicSharedMemorySize, G1_SMEM_BYTES);
    cudaFuncSetAttribute(k_layer2, cudaFuncAttributeMaxDynamicSharedMemorySize, L2_SMEM_BYTES);

    k_prep<<<KTOT / 2 + (HID * OUTD) / 1024, 256>>>(W1, W2);
    k_gemm1<<<256, 256, G1_SMEM_BYTES>>>(x, b1);
    k_layer2<<<128, 256, L2_SMEM_BYTES>>>(b2, (float*)d_out);
}